// round 7
// baseline (speedup 1.0000x reference)
#include <cuda_runtime.h>
#include <math.h>

#define H 4096
#define INV_SQRT_D (1.0f / 64.0f)
#define NROWS (4 * H + 2)

#define MV_BLOCKS 296          // 2 blocks/SM * 148 SMs, one wave (3/SM reg limit)
#define MV_WARPS  (MV_BLOCKS * 16)
#define UPD_BLOCKS 740         // 5 blocks/SM * 148 SMs, one wave

// ---------------- device scratch (allocation-free) ----------------
__device__ float g_q[H];
__device__ float g_k[H];     // already scaled by 1/sqrt(d)
__device__ float g_v[H];
__device__ float g_opre[H];  // Wo@x + bo (pre-sigmoid)
__device__ float g_dots[2];  // wi.x, wf.x
__device__ float g_sc[3];    // i_gate, f_gate, 1/denom

// ---------------- reductions ----------------
__device__ __forceinline__ float warp_reduce(float v) {
    #pragma unroll
    for (int o = 16; o > 0; o >>= 1)
        v += __shfl_down_sync(0xffffffffu, v, o);
    return v;
}

__device__ __forceinline__ float block_reduce_1024(float v) {
    __shared__ float s[32];
    int lane = threadIdx.x & 31;
    int wid  = threadIdx.x >> 5;
    v = warp_reduce(v);
    if (lane == 0) s[wid] = v;
    __syncthreads();
    if (wid == 0) {
        v = s[lane];
        v = warp_reduce(v);
    }
    return v; // valid in warp 0
}

// ---------------- kernel A: all matvecs + scalar-gate dots ----------------
// One-wave grid; warp-per-row with deterministic grid-stride over rows.
__global__ void __launch_bounds__(512)
matvec_kernel(const float* __restrict__ x,
              const float* __restrict__ Wq, const float* __restrict__ Wk,
              const float* __restrict__ Wv, const float* __restrict__ Wo,
              const float* __restrict__ bq, const float* __restrict__ bk,
              const float* __restrict__ bv, const float* __restrict__ bo,
              const float* __restrict__ wi, const float* __restrict__ wf) {
    int gw   = (blockIdx.x * 512 + threadIdx.x) >> 5;  // global warp id
    int lane = threadIdx.x & 31;
    const float4* x4 = (const float4*)x;

    for (int row = gw; row < NROWS; row += MV_WARPS) {
        const float* wrow;
        if      (row <     H) wrow = Wq + (size_t) row          * H;
        else if (row < 2 * H) wrow = Wk + (size_t)(row -   H)   * H;
        else if (row < 3 * H) wrow = Wv + (size_t)(row - 2*H)   * H;
        else if (row < 4 * H) wrow = Wo + (size_t)(row - 3*H)   * H;
        else                  wrow = (row == 4 * H) ? wi : wf;

        const float4* w4 = (const float4*)wrow;

        float s0 = 0.0f, s1 = 0.0f;
        #pragma unroll 8
        for (int i = 0; i < (H / 4) / 32; i += 2) {   // 32 f4 per lane
            int ia = lane + i * 32;
            int ib = lane + (i + 1) * 32;
            float4 wa = __ldcs(&w4[ia]);
            float4 wb = __ldcs(&w4[ib]);
            float4 xa = x4[ia];
            float4 xb = x4[ib];
            s0 += wa.x * xa.x + wa.y * xa.y + wa.z * xa.z + wa.w * xa.w;
            s1 += wb.x * xb.x + wb.y * xb.y + wb.z * xb.z + wb.w * xb.w;
        }
        float sum = warp_reduce(s0 + s1);

        if (lane == 0) {
            if      (row <     H) g_q[row]          = sum + bq[row];
            else if (row < 2 * H) g_k[row -   H]    = (sum + bk[row - H]) * INV_SQRT_D;
            else if (row < 3 * H) g_v[row - 2*H]    = sum + bv[row - 2*H];
            else if (row < 4 * H) g_opre[row - 3*H] = sum + bo[row - 3*H];
            else                  g_dots[row - 4*H] = sum;
        }
    }
}

// ---------------- kernel B: gates, n update, denom ----------------
__global__ void __launch_bounds__(1024)
gate_n_kernel(const float* __restrict__ n_prev,
              const float* __restrict__ bi, const float* __restrict__ bf,
              float* __restrict__ out_n) {
    __shared__ float s_ig, s_fg;
    int tid = threadIdx.x;
    if (tid == 0) {
        s_ig = expf(g_dots[0] + bi[0]);
        s_fg = 1.0f / (1.0f + expf(-(g_dots[1] + bf[0])));
    }
    __syncthreads();
    float ig = s_ig, fg = s_fg;

    float dot = 0.0f;
    #pragma unroll
    for (int i = 0; i < H / 1024; i++) {
        int j = tid + i * 1024;
        float nj = fg * n_prev[j] + ig * g_k[j];
        out_n[j] = nj;
        dot += nj * g_q[j];
    }
    dot = block_reduce_1024(dot);
    if (tid == 0) {
        float denom = fmaxf(fabsf(dot), 1.0f);
        g_sc[0] = ig;
        g_sc[1] = fg;
        g_sc[2] = 1.0f / denom;
    }
}

// ---------------- kernel C: C update + fused readout + output gate ----------
// One-wave grid (5 blocks/SM pinned); block-per-row grid-stride. k,q staged
// to smem once per block, amortized over ~5.5 rows.
__global__ void __launch_bounds__(256, 5)
update_kernel(const float* __restrict__ C_prev,
              float* __restrict__ out_h, float* __restrict__ out_C) {
    __shared__ float4 sk[H / 4];    // 16 KB
    __shared__ float4 sq[H / 4];    // 16 KB
    __shared__ float  red[8];

    int tid  = threadIdx.x;
    int lane = tid & 31;
    int wid  = tid >> 5;

    // stage k, q once per block
    const float4* k4 = (const float4*)g_k;
    const float4* q4 = (const float4*)g_q;
    #pragma unroll
    for (int i = 0; i < (H / 4) / 256; i++) {
        int idx = tid + i * 256;
        sk[idx] = k4[idx];
        sq[idx] = q4[idx];
    }
    __syncthreads();

    float ig = g_sc[0], fg = g_sc[1], invden = g_sc[2];

    for (int row = blockIdx.x; row < H; row += UPD_BLOCKS) {
        float ivr = ig * g_v[row];
        const float4* cp4 = (const float4*)(C_prev + (size_t)row * H);
        float4*       co4 = (float4*)      (out_C  + (size_t)row * H);

        float dot = 0.0f;
        #pragma unroll
        for (int i = 0; i < (H / 4) / 256; i++) {      // 4 iters
            int idx = tid + i * 256;
            float4 c  = __ldcs(&cp4[idx]);
            float4 kk = sk[idx];
            float4 cn;
            cn.x = fg * c.x + ivr * kk.x;
            cn.y = fg * c.y + ivr * kk.y;
            cn.z = fg * c.z + ivr * kk.z;
            cn.w = fg * c.w + ivr * kk.w;
            __stcs(&co4[idx], cn);
            float4 qq = sq[idx];
            dot += cn.x * qq.x + cn.y * qq.y + cn.z * qq.z + cn.w * qq.w;
        }

        dot = warp_reduce(dot);
        if (lane == 0) red[wid] = dot;
        __syncthreads();
        if (wid == 0 && lane == 0) {
            float t = red[0] + red[1] + red[2] + red[3]
                    + red[4] + red[5] + red[6] + red[7];
            float h_tilde = t * invden;
            float o = 1.0f / (1.0f + expf(-g_opre[row]));
            out_h[row] = o * h_tilde;
        }
        __syncthreads();   // red[] reusable next iteration
    }
}

// ---------------- launcher ----------------
extern "C" void kernel_launch(void* const* d_in, const int* in_sizes, int n_in,
                              void* d_out, int out_size) {
    const float* x      = (const float*)d_in[0];
    // d_in[1] = h_prev (unused by mLSTM math)
    const float* C_prev = (const float*)d_in[2];
    const float* n_prev = (const float*)d_in[3];
    const float* Wq     = (const float*)d_in[4];
    const float* Wk     = (const float*)d_in[5];
    const float* Wv     = (const float*)d_in[6];
    const float* Wo     = (const float*)d_in[7];
    const float* bq     = (const float*)d_in[8];
    const float* bk     = (const float*)d_in[9];
    const float* bv     = (const float*)d_in[10];
    const float* bo     = (const float*)d_in[11];
    const float* wi     = (const float*)d_in[12];
    const float* bi     = (const float*)d_in[13];
    const float* wf     = (const float*)d_in[14];
    const float* bf     = (const float*)d_in[15];

    float* out   = (float*)d_out;
    float* out_h = out;                      // [H]
    float* out_C = out + H;                  // [H, H]
    float* out_n = out + H + (size_t)H * H;  // [H]

    matvec_kernel<<<MV_BLOCKS, 512>>>(x, Wq, Wk, Wv, Wo, bq, bk, bv, bo, wi, wf);
    gate_n_kernel<<<1, 1024>>>(n_prev, bi, bf, out_n);
    update_kernel<<<UPD_BLOCKS, 256>>>(C_prev, out_h, out_C);
}

// round 9
// speedup vs baseline: 1.2140x; 1.2140x over previous
#include <cuda_runtime.h>
#include <math.h>

#define H 4096
#define INV_SQRT_D (1.0f / 64.0f)
#define NROWS (4 * H + 2)

// ---------------- device scratch (allocation-free) ----------------
__device__ float g_q[H];
__device__ float g_k[H];     // already scaled by 1/sqrt(d)
__device__ float g_v[H];
__device__ float g_opre[H];  // Wo@x + bo (pre-sigmoid)
__device__ float g_dots[2];  // wi.x, wf.x
__device__ float g_sc[3];    // i_gate, f_gate, 1/denom

// ---------------- reductions ----------------
__device__ __forceinline__ float warp_reduce(float v) {
    #pragma unroll
    for (int o = 16; o > 0; o >>= 1)
        v += __shfl_down_sync(0xffffffffu, v, o);
    return v;
}

__device__ __forceinline__ float block_reduce_1024(float v) {
    __shared__ float s[32];
    int lane = threadIdx.x & 31;
    int wid  = threadIdx.x >> 5;
    v = warp_reduce(v);
    if (lane == 0) s[wid] = v;
    __syncthreads();
    if (wid == 0) {
        v = s[lane];
        v = warp_reduce(v);
    }
    return v; // valid in warp 0
}

// ---------------- kernel A: all matvecs + scalar-gate dots ----------------
// One WARP per output row; 256-thread blocks (8 warp-rows) for fine-grained
// block retirement/refill. Inner loop identical to the best-measured (R2) form.
__global__ void __launch_bounds__(256)
matvec_kernel(const float* __restrict__ x,
              const float* __restrict__ Wq, const float* __restrict__ Wk,
              const float* __restrict__ Wv, const float* __restrict__ Wo,
              const float* __restrict__ bq, const float* __restrict__ bk,
              const float* __restrict__ bv, const float* __restrict__ bo,
              const float* __restrict__ wi, const float* __restrict__ wf) {
    int gw   = (blockIdx.x * 256 + threadIdx.x) >> 5;  // global warp id = row
    int lane = threadIdx.x & 31;
    if (gw >= NROWS) return;

    const float* wrow;
    if      (gw <     H) wrow = Wq + (size_t) gw          * H;
    else if (gw < 2 * H) wrow = Wk + (size_t)(gw -   H)   * H;
    else if (gw < 3 * H) wrow = Wv + (size_t)(gw - 2*H)   * H;
    else if (gw < 4 * H) wrow = Wo + (size_t)(gw - 3*H)   * H;
    else                 wrow = (gw == 4 * H) ? wi : wf;

    const float4* w4 = (const float4*)wrow;
    const float4* x4 = (const float4*)x;

    float s0 = 0.0f, s1 = 0.0f;
    #pragma unroll 8
    for (int i = 0; i < (H / 4) / 32; i += 2) {   // 32 f4 per lane
        int ia = lane + i * 32;
        int ib = lane + (i + 1) * 32;
        float4 wa = __ldcs(&w4[ia]);
        float4 wb = __ldcs(&w4[ib]);
        float4 xa = x4[ia];
        float4 xb = x4[ib];
        s0 += wa.x * xa.x + wa.y * xa.y + wa.z * xa.z + wa.w * xa.w;
        s1 += wb.x * xb.x + wb.y * xb.y + wb.z * xb.z + wb.w * xb.w;
    }
    float sum = warp_reduce(s0 + s1);

    if (lane == 0) {
        if      (gw <     H) g_q[gw]          = sum + bq[gw];
        else if (gw < 2 * H) g_k[gw -   H]    = (sum + bk[gw - H]) * INV_SQRT_D;
        else if (gw < 3 * H) g_v[gw - 2*H]    = sum + bv[gw - 2*H];
        else if (gw < 4 * H) g_opre[gw - 3*H] = sum + bo[gw - 3*H];
        else                 g_dots[gw - 4*H] = sum;
    }
}

// ---------------- kernel B: gates, n update, denom ----------------
__global__ void __launch_bounds__(1024)
gate_n_kernel(const float* __restrict__ n_prev,
              const float* __restrict__ bi, const float* __restrict__ bf,
              float* __restrict__ out_n) {
    __shared__ float s_ig, s_fg;
    int tid = threadIdx.x;
    if (tid == 0) {
        s_ig = expf(g_dots[0] + bi[0]);
        s_fg = 1.0f / (1.0f + expf(-(g_dots[1] + bf[0])));
    }
    __syncthreads();
    float ig = s_ig, fg = s_fg;

    float dot = 0.0f;
    #pragma unroll
    for (int i = 0; i < H / 1024; i++) {
        int j = tid + i * 1024;
        float nj = fg * n_prev[j] + ig * g_k[j];
        out_n[j] = nj;
        dot += nj * g_q[j];
    }
    dot = block_reduce_1024(dot);
    if (tid == 0) {
        float denom = fmaxf(fabsf(dot), 1.0f);
        g_sc[0] = ig;
        g_sc[1] = fg;
        g_sc[2] = 1.0f / denom;
    }
}

// ---------------- kernel C: C update + fused readout + output gate ----------
// One 128-thread BLOCK per C row (4096 blocks); 8 independent float4 loads
// per thread for deep MLP. Global (L2-hot) k,q loads; no smem staging.
__global__ void __launch_bounds__(128)
update_kernel(const float* __restrict__ C_prev,
              float* __restrict__ out_h, float* __restrict__ out_C) {
    __shared__ float red[4];
    int row  = blockIdx.x;
    int tid  = threadIdx.x;
    int lane = tid & 31;
    int wid  = tid >> 5;

    float ig = g_sc[0], fg = g_sc[1], invden = g_sc[2];
    float ivr = ig * g_v[row];

    const float4* cp4 = (const float4*)(C_prev + (size_t)row * H);
    float4*       co4 = (float4*)      (out_C  + (size_t)row * H);
    const float4* k4  = (const float4*)g_k;
    const float4* q4  = (const float4*)g_q;

    float dot = 0.0f;
    #pragma unroll
    for (int i = 0; i < (H / 4) / 128; i++) {   // 8 iters, front-batched LDGs
        int idx = tid + i * 128;
        float4 c  = __ldcs(&cp4[idx]);
        float4 kk = k4[idx];
        float4 cn;
        cn.x = fg * c.x + ivr * kk.x;
        cn.y = fg * c.y + ivr * kk.y;
        cn.z = fg * c.z + ivr * kk.z;
        cn.w = fg * c.w + ivr * kk.w;
        __stcs(&co4[idx], cn);
        float4 qq = q4[idx];
        dot += cn.x * qq.x + cn.y * qq.y + cn.z * qq.z + cn.w * qq.w;
    }

    dot = warp_reduce(dot);
    if (lane == 0) red[wid] = dot;
    __syncthreads();
    if (tid == 0) {
        float t = red[0] + red[1] + red[2] + red[3];
        float h_tilde = t * invden;
        float o = 1.0f / (1.0f + expf(-g_opre[row]));
        out_h[row] = o * h_tilde;
    }
}

// ---------------- launcher ----------------
extern "C" void kernel_launch(void* const* d_in, const int* in_sizes, int n_in,
                              void* d_out, int out_size) {
    const float* x      = (const float*)d_in[0];
    // d_in[1] = h_prev (unused by mLSTM math)
    const float* C_prev = (const float*)d_in[2];
    const float* n_prev = (const float*)d_in[3];
    const float* Wq     = (const float*)d_in[4];
    const float* Wk     = (const float*)d_in[5];
    const float* Wv     = (const float*)d_in[6];
    const float* Wo     = (const float*)d_in[7];
    const float* bq     = (const float*)d_in[8];
    const float* bk     = (const float*)d_in[9];
    const float* bv     = (const float*)d_in[10];
    const float* bo     = (const float*)d_in[11];
    const float* wi     = (const float*)d_in[12];
    const float* bi     = (const float*)d_in[13];
    const float* wf     = (const float*)d_in[14];
    const float* bf     = (const float*)d_in[15];

    float* out   = (float*)d_out;
    float* out_h = out;                      // [H]
    float* out_C = out + H;                  // [H, H]
    float* out_n = out + H + (size_t)H * H;  // [H]

    int mv_blocks = (NROWS + 7) / 8;         // 8 warp-rows per 256-thread block
    matvec_kernel<<<mv_blocks, 256>>>(x, Wq, Wk, Wv, Wo, bq, bk, bv, bo, wi, wf);
    gate_n_kernel<<<1, 1024>>>(n_prev, bi, bf, out_n);
    update_kernel<<<H, 128>>>(C_prev, out_h, out_C);
}

// round 10
// speedup vs baseline: 1.2474x; 1.0275x over previous
#include <cuda_runtime.h>
#include <math.h>

#define H 4096
#define INV_SQRT_D (1.0f / 64.0f)
#define NROWS (4 * H + 2)

// ---------------- device scratch (allocation-free) ----------------
__device__ float g_q[H];
__device__ float g_k[H];     // already scaled by 1/sqrt(d)
__device__ float g_v[H];
__device__ float g_opre[H];  // Wo@x + bo (pre-sigmoid)
__device__ float g_dots[2];  // wi.x, wf.x
__device__ float g_inv;      // 1/denom (published by update block 0)
__device__ int   g_flag;     // g_inv ready flag (reset by matvec each launch)

// ---------------- reductions ----------------
__device__ __forceinline__ float warp_reduce(float v) {
    #pragma unroll
    for (int o = 16; o > 0; o >>= 1)
        v += __shfl_down_sync(0xffffffffu, v, o);
    return v;
}

// ---------------- kernel A: all matvecs + scalar-gate dots ----------------
// One WARP per output row; 256-thread blocks (8 warp-rows). Best-measured form.
__global__ void __launch_bounds__(256)
matvec_kernel(const float* __restrict__ x,
              const float* __restrict__ Wq, const float* __restrict__ Wk,
              const float* __restrict__ Wv, const float* __restrict__ Wo,
              const float* __restrict__ bq, const float* __restrict__ bk,
              const float* __restrict__ bv, const float* __restrict__ bo,
              const float* __restrict__ wi, const float* __restrict__ wf) {
    if (blockIdx.x == 0 && threadIdx.x == 0) g_flag = 0;  // reset for this replay

    int gw   = (blockIdx.x * 256 + threadIdx.x) >> 5;  // global warp id = row
    int lane = threadIdx.x & 31;
    if (gw >= NROWS) return;

    const float* wrow;
    if      (gw <     H) wrow = Wq + (size_t) gw          * H;
    else if (gw < 2 * H) wrow = Wk + (size_t)(gw -   H)   * H;
    else if (gw < 3 * H) wrow = Wv + (size_t)(gw - 2*H)   * H;
    else if (gw < 4 * H) wrow = Wo + (size_t)(gw - 3*H)   * H;
    else                 wrow = (gw == 4 * H) ? wi : wf;

    const float4* w4 = (const float4*)wrow;
    const float4* x4 = (const float4*)x;

    float s0 = 0.0f, s1 = 0.0f;
    #pragma unroll 8
    for (int i = 0; i < (H / 4) / 32; i += 2) {   // 32 f4 per lane
        int ia = lane + i * 32;
        int ib = lane + (i + 1) * 32;
        float4 wa = __ldcs(&w4[ia]);
        float4 wb = __ldcs(&w4[ib]);
        float4 xa = x4[ia];
        float4 xb = x4[ib];
        s0 += wa.x * xa.x + wa.y * xa.y + wa.z * xa.z + wa.w * xa.w;
        s1 += wb.x * xb.x + wb.y * xb.y + wb.z * xb.z + wb.w * xb.w;
    }
    float sum = warp_reduce(s0 + s1);

    if (lane == 0) {
        if      (gw <     H) g_q[gw]          = sum + bq[gw];
        else if (gw < 2 * H) g_k[gw -   H]    = (sum + bk[gw - H]) * INV_SQRT_D;
        else if (gw < 3 * H) g_v[gw - 2*H]    = sum + bv[gw - 2*H];
        else if (gw < 4 * H) g_opre[gw - 3*H] = sum + bo[gw - 3*H];
        else                 g_dots[gw - 4*H] = sum;
    }
}

// ---------------- kernel B: C update + n/gates/denom (block 0) + readout ----
// One 256-thread BLOCK per C row (R1's best-measured form). Gate scalars are
// recomputed per block (2 loads + exp: free). Block 0 additionally does the
// n update + denom and publishes 1/denom via flag; consumers read it only at
// their final instruction, so the spin is ~always already satisfied.
__global__ void __launch_bounds__(256)
update_kernel(const float* __restrict__ C_prev,
              const float* __restrict__ n_prev,
              const float* __restrict__ bi, const float* __restrict__ bf,
              float* __restrict__ out_h, float* __restrict__ out_C,
              float* __restrict__ out_n) {
    __shared__ float red[8];
    int row  = blockIdx.x;
    int tid  = threadIdx.x;
    int lane = tid & 31;
    int wid  = tid >> 5;

    // gate scalars: uniform, cheap
    float ig = expf(g_dots[0] + bi[0]);
    float fg = 1.0f / (1.0f + expf(-(g_dots[1] + bf[0])));

    if (row == 0) {
        // n = fg*n_prev + ig*k ; denom = max(|n.q|, 1) ; publish 1/denom
        const float4* k4  = (const float4*)g_k;
        const float4* q4  = (const float4*)g_q;
        const float4* np4 = (const float4*)n_prev;
        float4*       on4 = (float4*)out_n;
        float nd = 0.0f;
        #pragma unroll
        for (int i = 0; i < (H / 4) / 256; i++) {
            int idx = tid + i * 256;
            float4 kk = k4[idx];
            float4 qq = q4[idx];
            float4 np = np4[idx];
            float4 nn;
            nn.x = fg * np.x + ig * kk.x;
            nn.y = fg * np.y + ig * kk.y;
            nn.z = fg * np.z + ig * kk.z;
            nn.w = fg * np.w + ig * kk.w;
            on4[idx] = nn;
            nd += nn.x * qq.x + nn.y * qq.y + nn.z * qq.z + nn.w * qq.w;
        }
        nd = warp_reduce(nd);
        if (lane == 0) red[wid] = nd;
        __syncthreads();
        if (tid == 0) {
            float t = red[0] + red[1] + red[2] + red[3]
                    + red[4] + red[5] + red[6] + red[7];
            g_inv = 1.0f / fmaxf(fabsf(t), 1.0f);
            __threadfence();
            atomicExch(&g_flag, 1);
        }
        __syncthreads();   // red[] reusable below
    }

    // main pass: stream C_prev -> C, fused dot with q (R1 form)
    float ivr = ig * g_v[row];
    const float4* cp4 = (const float4*)(C_prev + (size_t)row * H);
    float4*       co4 = (float4*)      (out_C  + (size_t)row * H);
    const float4* k4  = (const float4*)g_k;
    const float4* q4  = (const float4*)g_q;

    float dot = 0.0f;
    #pragma unroll
    for (int i = 0; i < (H / 4) / 256; i++) {   // 4 iters
        int idx = tid + i * 256;
        float4 c  = __ldcs(&cp4[idx]);
        float4 kk = k4[idx];
        float4 qq = q4[idx];
        float4 cn;
        cn.x = fg * c.x + ivr * kk.x;
        cn.y = fg * c.y + ivr * kk.y;
        cn.z = fg * c.z + ivr * kk.z;
        cn.w = fg * c.w + ivr * kk.w;
        __stcs(&co4[idx], cn);
        dot += cn.x * qq.x + cn.y * qq.y + cn.z * qq.z + cn.w * qq.w;
    }
    dot = warp_reduce(dot);
    if (lane == 0) red[wid] = dot;
    __syncthreads();
    if (tid == 0) {
        float t = red[0] + red[1] + red[2] + red[3]
                + red[4] + red[5] + red[6] + red[7];
        // wait for 1/denom (block 0 published long ago in the common case)
        while (atomicAdd(&g_flag, 0) == 0) __nanosleep(40);
        float invden = __ldcg(&g_inv);
        float h_tilde = t * invden;
        float o = 1.0f / (1.0f + expf(-g_opre[row]));
        out_h[row] = o * h_tilde;
    }
}

// ---------------- launcher ----------------
extern "C" void kernel_launch(void* const* d_in, const int* in_sizes, int n_in,
                              void* d_out, int out_size) {
    const float* x      = (const float*)d_in[0];
    // d_in[1] = h_prev (unused by mLSTM math)
    const float* C_prev = (const float*)d_in[2];
    const float* n_prev = (const float*)d_in[3];
    const float* Wq     = (const float*)d_in[4];
    const float* Wk     = (const float*)d_in[5];
    const float* Wv     = (const float*)d_in[6];
    const float* Wo     = (const float*)d_in[7];
    const float* bq     = (const float*)d_in[8];
    const float* bk     = (const float*)d_in[9];
    const float* bv     = (const float*)d_in[10];
    const float* bo     = (const float*)d_in[11];
    const float* wi     = (const float*)d_in[12];
    const float* bi     = (const float*)d_in[13];
    const float* wf     = (const float*)d_in[14];
    const float* bf     = (const float*)d_in[15];

    float* out   = (float*)d_out;
    float* out_h = out;                      // [H]
    float* out_C = out + H;                  // [H, H]
    float* out_n = out + H + (size_t)H * H;  // [H]

    int mv_blocks = (NROWS + 7) / 8;         // 8 warp-rows per 256-thread block
    matvec_kernel<<<mv_blocks, 256>>>(x, Wq, Wk, Wv, Wo, bq, bk, bv, bo, wi, wf);
    update_kernel<<<H, 256>>>(C_prev, n_prev, bi, bf, out_h, out_C, out_n);
}